// round 15
// baseline (speedup 1.0000x reference)
#include <cuda_runtime.h>
#include <cuda_bf16.h>
#include <cstdint>

#define NM     512
#define BATCH  32
#define DIMK   64
#define BIGF   1e30f
#define SENTU  0x7fc00000u

// Packed D (pre-scaled by log2 e): g_Dq[b][W][u][k] as float2.
// W = warp row-group (rows 64W+2k, 64W+2k+1), u = local step, col j = u-2k.
#define UROWS 592
__device__ __align__(16) float g_Dq[(size_t)BATCH * 8 * UROWS * 64];

// Per-tile ready flags: g_flag[b*64 + W*8 + jt]. BSS zero; reset by consumer.
__device__ int g_flag[BATCH * 64];

// Boundary rings: producer (warp w) publishes v1(u-1) at slot u.
// value(col c) lives at slot c+63. Slots 0..575 written; rest preinit BIG.
#define RING 656

__device__ __forceinline__ float ex2f(float x) {
    float r; asm("ex2.approx.f32 %0, %1;" : "=f"(r) : "f"(x)); return r;
}
__device__ __forceinline__ float lg2f(float x) {
    float r; asm("lg2.approx.f32 %0, %1;" : "=f"(r) : "f"(x)); return r;
}
// smem spin (raw backward branch, no BSSY): wait until *p != sentinel.
__device__ __forceinline__ float spinv(const float* p) {
    unsigned a = (unsigned)__cvta_generic_to_shared(p);
    unsigned v;
    asm volatile(
        "{\n\t.reg .pred sp;\n"
        "SPINS%=:\n\t"
        "ld.volatile.shared.b32 %0, [%1];\n\t"
        "setp.eq.u32 sp, %0, 0x7fc00000;\n\t"
        "@sp bra SPINS%=;\n\t}"
        : "=r"(v) : "r"(a) : "memory");
    return __uint_as_float(v);
}
__device__ __forceinline__ void sts_vol(float* p, float v) {
    unsigned a = (unsigned)__cvta_generic_to_shared(p);
    asm volatile("st.volatile.shared.b32 [%0], %1;" :: "r"(a), "f"(v) : "memory");
}
__device__ __forceinline__ int ldacq(const int* p) {
    int v;
    asm volatile("ld.acquire.gpu.global.b32 %0, [%1];" : "=r"(v) : "l"(p) : "memory");
    return v;
}
__device__ __forceinline__ void spin_flag(const int* p) {
    int v;
    asm volatile(
        "{\n\t.reg .pred fp;\n"
        "FSPIN%=:\n\t"
        "ld.acquire.gpu.global.b32 %0, [%1];\n\t"
        "setp.eq.s32 fp, %0, 0;\n\t"
        "@fp bra FSPIN%=;\n\t}"
        : "=r"(v) : "l"(p) : "memory");
}

union SmemU {
    struct {
        float Xs[64 * 68];
        float Ys[64 * 68];
        float x2s[64];
        float y2s[64];
        float stage[64 * 66];
    } pd;
    float rings[9 * RING];
};

// ---------------------------------------------------------------------------
// Fused kernel. Blocks 0..31: persistent sdtw wavefront CTAs (one per batch).
// Blocks 32..2079: pairdist tiles, j-tile outermost so early columns land
// first. Producer->consumer handoff via acquire flags, polled 64 steps early.
// ---------------------------------------------------------------------------
__global__ void __launch_bounds__(256) fused_kernel(
    const float* __restrict__ X, const float* __restrict__ Y,
    float* __restrict__ out)
{
    __shared__ SmemU smem;
    const int bid = blockIdx.x;
    const int tid = threadIdx.x;

    if (bid >= 32) {
        // =================== pairdist tile ===================
        const int p  = bid - 32;
        const int jt = p >> 8;          // j-tile, outermost in schedule
        const int b  = (p >> 3) & 31;
        const int W  = p & 7;           // i-tile == warp row-group
        const int i0 = W * 64;
        const int j0 = jt * 64;

        float* Xs = smem.pd.Xs;
        float* Ys = smem.pd.Ys;
        float* x2s = smem.pd.x2s;
        float* y2s = smem.pd.y2s;
        float* stage = smem.pd.stage;

        const float* Xb = X + ((size_t)b * NM + i0) * DIMK;
        const float* Yb = Y + ((size_t)b * NM + j0) * DIMK;

        for (int t = tid; t < 64 * 64; t += 256) {
            int r = t >> 6, k = t & 63;
            Xs[k * 68 + r] = Xb[r * DIMK + k];
            Ys[k * 68 + r] = Yb[r * DIMK + k];
        }
        __syncthreads();

        if (tid < 128) {
            int r = tid & 63;
            const float* S = (tid < 64) ? Xs : Ys;
            float acc = 0.f;
            #pragma unroll 8
            for (int k = 0; k < 64; ++k) { float v = S[k * 68 + r]; acc += v * v; }
            if (tid < 64) x2s[r] = acc; else y2s[r] = acc;
        }
        __syncthreads();

        const int tx = tid & 15, ty = tid >> 4;
        float acc[4][4];
        #pragma unroll
        for (int a = 0; a < 4; ++a)
            #pragma unroll
            for (int c = 0; c < 4; ++c) acc[a][c] = 0.f;

        #pragma unroll 8
        for (int k = 0; k < 64; ++k) {
            float4 xv = *(const float4*)&Xs[k * 68 + 4 * tx];
            float4 yv = *(const float4*)&Ys[k * 68 + 4 * ty];
            float xr[4] = {xv.x, xv.y, xv.z, xv.w};
            float yr[4] = {yv.x, yv.y, yv.z, yv.w};
            #pragma unroll
            for (int jj = 0; jj < 4; ++jj)
                #pragma unroll
                for (int ii = 0; ii < 4; ++ii)
                    acc[jj][ii] += yr[jj] * xr[ii];
        }

        const float L2E = 1.4426950408889634f;
        float4 x2v = *(const float4*)&x2s[4 * tx];
        float xr2[4] = {x2v.x, x2v.y, x2v.z, x2v.w};
        #pragma unroll
        for (int jj = 0; jj < 4; ++jj) {
            float y2 = y2s[4 * ty + jj];
            #pragma unroll
            for (int ii = 0; ii < 4; ++ii)
                stage[(4 * ty + jj) * 66 + 4 * tx + ii] =
                    (xr2[ii] + y2 - 2.f * acc[jj][ii]) * L2E;
        }
        __syncthreads();

        // Packed writeout: local step row c = jl + 2k; lane = k.
        const int wk   = tid >> 5;
        const int lane = tid & 31;
        float2* gout = (float2*)g_Dq + ((size_t)(b * 8 + W) * UROWS + j0) * 32;
        for (int c = wk; c < 126; c += 8) {
            int jl = c - 2 * lane;
            if ((unsigned)jl < 64u) {
                float2 q = *(const float2*)&stage[jl * 66 + 2 * lane];
                gout[(size_t)c * 32 + lane] = q;
            }
        }

        __syncthreads();
        __threadfence();
        if (tid == 0)
            *(volatile int*)&g_flag[b * 64 + W * 8 + jt] = 1;
        return;
    }

    // =================== sdtw wavefront (R11 core) ===================
    float* rings = smem.rings;
    const int b    = bid;
    const int w    = tid >> 5;
    const int lane = tid & 31;
    const bool is0  = (lane == 0);
    const bool is31 = (lane == 31);

    for (int t = tid; t < 9 * RING; t += 256) {
        int r = t / RING, s = t % RING;
        bool sent = (r >= 1) && (s < 576);
        rings[t] = sent ? __uint_as_float(SENTU) : BIGF;
    }
    __syncthreads();

    const int* flagp = g_flag + b * 64 + w * 8;
    spin_flag(flagp + 0);                        // tile 0 covers rows 0..125

    // D prefetch ring (float2 per lane per step).
    const float2* dp0 = (const float2*)g_Dq + (size_t)(b * 8 + w) * UROWS * 32 + lane;
    float2 dring[8];
    #pragma unroll
    for (int p = 0; p < 8; ++p) dring[p] = dp0[p * 32];
    const float2* dp = dp0 + 8 * 32;

    const float* rring = rings + w * RING;        // consumer: value(col c) at slot c+63
    float*       wring = rings + (w + 1) * RING;  // producer: iter u writes slot u

    // Prefill: P(-1) at slot 62, P(0) at slot 63.
    float pm1 = spinv(rring + 62);
    float p0  = spinv(rring + 63);
    if (lane != 0) { pm1 = BIGF; p0 = BIGF; }
    if (w == 0 && lane == 0) pm1 = 0.0f;          // origin: R[-1][-1] = 0
    float lo0  = fminf(pm1, p0), hi0 = fmaxf(pm1, p0);
    float pNow = p0;

    // First chunk: slots 64..71 = P(1..8).
    float bnd[8];
    {
        (void)spinv(rring + 71);
        float4 c0 = *(const float4*)(rring + 64);
        float4 c1 = *(const float4*)(rring + 68);
        bnd[0]=c0.x; bnd[1]=c0.y; bnd[2]=c0.z; bnd[3]=c0.w;
        bnd[4]=c1.x; bnd[5]=c1.y; bnd[6]=c1.z; bnd[7]=c1.w;
    }

    float v0p  = BIGF;                 // v0(u-1)
    float d2yp = 0.f;                  // d(u-1).y
    float lo1p = BIGF, hi1p = BIGF;    // min/max(v0(u-2), v1(u-2))
    float res  = 0.f;
    int   fpre = 1;                    // early-loaded flag for next tile

    for (int B = 0; B < 576; B += 8) {
        // Gate D prefetch on tile flags, polled 64 steps early (off-chain).
        if ((B & 63) == 0 && B < 448) fpre = ldacq(flagp + (B >> 6) + 1);
        if ((B & 63) == 56 && B < 448) { if (fpre == 0) spin_flag(flagp + ((B + 8) >> 6)); }

        #pragma unroll
        for (int x = 0; x < 8; ++x) {
            float2 d2 = dring[x];
            dring[x] = dp[x * 32];                 // prefetch step u+8

            // cell0(u): softmin(P(j-1), P(j), v0(u-1))
            float m0 = fminf(lo0, v0p);
            float x0 = fmaxf(lo0, v0p);
            float v0 = (d2.x + m0) - lg2f(ex2f(m0 - x0) + ex2f(m0 - hi0) + 1.0f);

            // cell1(u-1): softmin(v0(u-2), v1(u-2), v0(u-1)) -- parallel chain
            float m1  = fminf(lo1p, v0p);
            float x1  = fmaxf(lo1p, v0p);
            float v1m = (d2yp + m1) - lg2f(ex2f(m1 - x1) + ex2f(m1 - hi1p) + 1.0f);

            if (x == 6) { if (B == 568) res = v1m; }   // iter 574 -> v1(573) = R[511][511]

            if (is31) sts_vol(wring + (B + x), v1m);   // publish slot u

            float sh = __shfl_up_sync(0xffffffffu, v1m, 1);
            float newv = is0 ? bnd[x] : sh;            // P(u+1)

            if (x == 7) {                              // next chunk: slots B+72..79
                (void)spinv(rring + B + 79);
                float4 c0 = *(const float4*)(rring + B + 72);
                float4 c1 = *(const float4*)(rring + B + 76);
                bnd[0]=c0.x; bnd[1]=c0.y; bnd[2]=c0.z; bnd[3]=c0.w;
                bnd[4]=c1.x; bnd[5]=c1.y; bnd[6]=c1.z; bnd[7]=c1.w;
            }

            // rolls (off the v0 chain)
            lo1p = fminf(v0p, v1m);
            hi1p = fmaxf(v0p, v1m);
            lo0  = fminf(pNow, newv);
            hi0  = fmaxf(pNow, newv);
            pNow = newv;
            v0p  = v0;
            d2yp = d2.y;
        }
        dp += 8 * 32;
    }

    if (tid == 255)
        out[b] = res * 0.69314718055994531f;           // log2 -> natural domain

    // Reset this batch's flags so graph replays start clean.
    __syncthreads();
    if (tid < 64) g_flag[b * 64 + tid] = 0;
}

extern "C" void kernel_launch(void* const* d_in, const int* in_sizes, int n_in,
                              void* d_out, int out_size)
{
    (void)in_sizes; (void)n_in; (void)out_size;
    const float* X = (const float*)d_in[0];
    const float* Y = (const float*)d_in[1];
    float* out = (float*)d_out;

    fused_kernel<<<32 + BATCH * 64, 256>>>(X, Y, out);
}

// round 16
// speedup vs baseline: 1.0847x; 1.0847x over previous
#include <cuda_runtime.h>
#include <cuda_bf16.h>
#include <cstdint>

#define NM     512
#define BATCH  32
#define DIMK   64
#define BIGF   1e30f
#define SENTU  0x7fc00000u

// Anti-diagonal packed D (pre-scaled by log2 e): g_Dr[b][W][u][ilg],
// W = 128-row warp group, ilg = row within group, col j = u - ilg.
// Unwritten (invalid col) slots stay zero (BSS).
#define UR 648
__device__ __align__(16) float g_Dr[(size_t)BATCH * 4 * UR * 128];

// Boundary rings: producer warp w publishes n3(u) (row 128w+127, col u-127)
// at slot u. P(c) lives at slot c+127. Written slots 0..639.
#define RING 784

__device__ __forceinline__ float ex2f(float x) {
    float r; asm("ex2.approx.f32 %0, %1;" : "=f"(r) : "f"(x)); return r;
}
__device__ __forceinline__ float lg2f(float x) {
    float r; asm("lg2.approx.f32 %0, %1;" : "=f"(r) : "f"(x)); return r;
}
// smem spin (raw backward branch, no BSSY): wait until *p != sentinel.
__device__ __forceinline__ float spinv(const float* p) {
    unsigned a = (unsigned)__cvta_generic_to_shared(p);
    unsigned v;
    asm volatile(
        "{\n\t.reg .pred sp;\n"
        "SPINS%=:\n\t"
        "ld.volatile.shared.b32 %0, [%1];\n\t"
        "setp.eq.u32 sp, %0, 0x7fc00000;\n\t"
        "@sp bra SPINS%=;\n\t}"
        : "=r"(v) : "r"(a) : "memory");
    return __uint_as_float(v);
}
__device__ __forceinline__ void sts_vol(float* p, float v) {
    unsigned a = (unsigned)__cvta_generic_to_shared(p);
    asm volatile("st.volatile.shared.b32 [%0], %1;" :: "r"(a), "f"(v) : "memory");
}

// ---------------------------------------------------------------------------
// Kernel 1: pairwise sqdist * log2(e) packed into g_Dr (anti-diagonal).
// 64x64 tiles, 256 threads, 4x4 microtiles; stage aliases Xs/Ys.
// ---------------------------------------------------------------------------
__global__ void __launch_bounds__(256) pairdist_kernel(
    const float* __restrict__ X, const float* __restrict__ Y)
{
    __shared__ __align__(16) float XsYs[2 * 64 * 68];
    __shared__ __align__(16) float x2s[64];
    __shared__ __align__(16) float y2s[64];
    float* Xs = XsYs;
    float* Ys = XsYs + 64 * 68;

    const int b  = blockIdx.z;
    const int i0 = blockIdx.x * 64;
    const int j0 = blockIdx.y * 64;
    const int W      = blockIdx.x >> 1;          // 128-row group
    const int half64 = (blockIdx.x & 1) * 64;
    const int tid = threadIdx.x;

    const float* Xb = X + ((size_t)b * NM + i0) * DIMK;
    const float* Yb = Y + ((size_t)b * NM + j0) * DIMK;

    for (int t = tid; t < 64 * 64; t += 256) {
        int r = t >> 6, k = t & 63;
        Xs[k * 68 + r] = Xb[r * DIMK + k];
        Ys[k * 68 + r] = Yb[r * DIMK + k];
    }
    __syncthreads();

    if (tid < 128) {
        int r = tid & 63;
        const float* S = (tid < 64) ? Xs : Ys;
        float acc = 0.f;
        #pragma unroll 8
        for (int k = 0; k < 64; ++k) { float v = S[k * 68 + r]; acc += v * v; }
        if (tid < 64) x2s[r] = acc; else y2s[r] = acc;
    }
    __syncthreads();

    const int tx = tid & 15, ty = tid >> 4;
    float acc[4][4];
    #pragma unroll
    for (int a = 0; a < 4; ++a)
        #pragma unroll
        for (int c = 0; c < 4; ++c) acc[a][c] = 0.f;

    #pragma unroll 8
    for (int k = 0; k < 64; ++k) {
        float4 xv = *(const float4*)&Xs[k * 68 + 4 * tx];
        float4 yv = *(const float4*)&Ys[k * 68 + 4 * ty];
        float xr[4] = {xv.x, xv.y, xv.z, xv.w};
        float yr[4] = {yv.x, yv.y, yv.z, yv.w};
        #pragma unroll
        for (int jj = 0; jj < 4; ++jj)
            #pragma unroll
            for (int ii = 0; ii < 4; ++ii)
                acc[jj][ii] += yr[jj] * xr[ii];
    }

    const float L2E = 1.4426950408889634f;
    float4 x2v = *(const float4*)&x2s[4 * tx];
    float xr2[4] = {x2v.x, x2v.y, x2v.z, x2v.w};
    float outv[4][4];
    #pragma unroll
    for (int jj = 0; jj < 4; ++jj) {
        float y2 = y2s[4 * ty + jj];
        #pragma unroll
        for (int ii = 0; ii < 4; ++ii)
            outv[jj][ii] = (xr2[ii] + y2 - 2.f * acc[jj][ii]) * L2E;
    }
    __syncthreads();                 // all Xs/Ys reads done -> reuse as stage

    // stage[ur][il], ur = il + jl (0..126), stride 68. 127*68=8636 <= 8704.
    float* stage = XsYs;
    #pragma unroll
    for (int jj = 0; jj < 4; ++jj)
        #pragma unroll
        for (int ii = 0; ii < 4; ++ii) {
            int il = 4 * tx + ii, jl = 4 * ty + jj;
            stage[(il + jl) * 68 + il] = outv[jj][ii];
        }
    __syncthreads();

    // Writeout: row ur -> u_global = j0 + half64 + ur, slots half64+il,
    // valid where jl = ur - il in [0,64). Contiguous coalesced runs.
    const int wk   = tid >> 5;
    const int lane = tid & 31;
    float* gout = g_Dr + (size_t)(b * 4 + W) * UR * 128;
    for (int ur = wk; ur < 127; ur += 8) {
        float* dst = gout + (size_t)(j0 + half64 + ur) * 128 + half64;
        #pragma unroll
        for (int pass = 0; pass < 2; ++pass) {
            int il = lane + 32 * pass;
            int jl = ur - il;
            if ((unsigned)jl < 64u)
                dst[il] = stage[ur * 68 + il];
        }
    }
}

// ---------------------------------------------------------------------------
// Kernel 2: soft-DTW wavefront. 1 CTA/batch, 4 warps x 32 lanes; lane k of
// warp w owns rows 128w+4k..+3. Iteration u computes cols u-4k-d for d=0..3:
// four INDEPENDENT softmins (deps only on iterations u-1/u-2) -> 12 MUFUs
// pipeline within one warp; loop chain = 52 cyc. Seams via smem rings.
// ---------------------------------------------------------------------------
__global__ void __launch_bounds__(128, 1) sdtw_kernel(float* __restrict__ out)
{
    __shared__ __align__(16) float rings[5][RING];   // ring 4 = sink

    const int b    = blockIdx.x;
    const int tid  = threadIdx.x;
    const int w    = tid >> 5;
    const int lane = tid & 31;
    const bool is0  = (lane == 0);
    const bool is31 = (lane == 31);

    // rings 1..3: sentinel for slots <= 638 (all written slots a consumer can
    // race on), BIG elsewhere. ring 0 (no producer) and ring 4 (sink): BIG.
    for (int t = tid; t < 5 * RING; t += 128) {
        int r = t / RING, s = t % RING;
        bool sent = (r >= 1) && (r <= 3) && (s <= 638);
        rings[0][t] = sent ? __uint_as_float(SENTU) : BIGF;
    }
    __syncthreads();

    // D prefetch ring: float4 per lane per iteration (rows 4k..4k+3).
    const float4* dp0 = (const float4*)g_Dr + (size_t)(b * 4 + w) * UR * 32 + lane;
    float4 dring[8];
    #pragma unroll
    for (int p = 0; p < 8; ++p) dring[p] = dp0[p * 32];
    const float4* dp = dp0 + 8 * 32;

    const float* rring = rings[w];       // consumer: P(c) at slot c+127
    float*       wring = rings[w + 1];   // producer: iter u writes slot u

    // Prefill: P(-1) at slot 126, P(0) at slot 127.
    float pm1 = spinv(rring + 126);
    float p0  = spinv(rring + 127);
    if (lane != 0) { pm1 = BIGF; p0 = BIGF; }
    if (w == 0 && lane == 0) pm1 = 0.0f;        // origin: R[-1][-1] = 0
    float lo0 = fminf(pm1, p0), hi0 = fmaxf(pm1, p0);
    float shvOld = p0;                          // P(0) / BIG

    // First chunk: slots 128..135 = P(1..8)  (newv(u) = P(u+1), u=0..7)
    float bnd[8];
    {
        (void)spinv(rring + 135);
        float4 c0 = *(const float4*)(rring + 128);
        float4 c1 = *(const float4*)(rring + 132);
        bnd[0]=c0.x; bnd[1]=c0.y; bnd[2]=c0.z; bnd[3]=c0.w;
        bnd[4]=c1.x; bnd[5]=c1.y; bnd[6]=c1.z; bnd[7]=c1.w;
    }

    float n0 = BIGF, n1 = BIGF, n2 = BIGF, n3 = BIGF;      // v_d(u-1)
    float lo1 = BIGF, hi1 = BIGF;
    float lo2 = BIGF, hi2 = BIGF;
    float lo3 = BIGF, hi3 = BIGF;
    float res = 0.f;

    for (int B = 0; B < 640; B += 8) {
        #pragma unroll
        for (int x = 0; x < 8; ++x) {
            float4 d4 = dring[x];
            dring[x] = dp[x * 32];                 // prefetch iteration u+8

            // 4 independent softmins (deps: iteration u-1 state only)
            float m0 = fminf(lo0, n0);
            float a0 = fmaxf(lo0, n0);
            float t0 = (d4.x + m0) - lg2f(ex2f(m0 - a0) + ex2f(m0 - hi0) + 1.0f);

            float m1 = fminf(lo1, n1);
            float a1 = fmaxf(lo1, n1);
            float t1 = (d4.y + m1) - lg2f(ex2f(m1 - a1) + ex2f(m1 - hi1) + 1.0f);

            float m2 = fminf(lo2, n2);
            float a2 = fmaxf(lo2, n2);
            float t2 = (d4.z + m2) - lg2f(ex2f(m2 - a2) + ex2f(m2 - hi2) + 1.0f);

            float m3 = fminf(lo3, n3);
            float a3 = fmaxf(lo3, n3);
            float t3 = (d4.w + m3) - lg2f(ex2f(m3 - a3) + ex2f(m3 - hi3) + 1.0f);

            if (x == 6) { if (B == 632) res = t3; }   // u=638: row 511, col 511

            if (is31) sts_vol(wring + (B + x), t3);   // publish row 128w+127

            float sh  = __shfl_up_sync(0xffffffffu, t3, 1);
            float shv = is0 ? bnd[x] : sh;            // up0 for iteration u+1

            if (x == 7) {                             // next chunk: slots B+136..143
                int sp = B + 143; if (sp > 638) sp = 638;
                (void)spinv(rring + sp);
                float4 c0 = *(const float4*)(rring + B + 136);
                float4 c1 = *(const float4*)(rring + B + 140);
                bnd[0]=c0.x; bnd[1]=c0.y; bnd[2]=c0.z; bnd[3]=c0.w;
                bnd[4]=c1.x; bnd[5]=c1.y; bnd[6]=c1.z; bnd[7]=c1.w;
            }

            // rolls (off the softmin chains)
            lo1 = fminf(n0, t0); hi1 = fmaxf(n0, t0);   // (diag,up) for cell1 @u+1
            lo2 = fminf(n1, t1); hi2 = fmaxf(n1, t1);
            lo3 = fminf(n2, t2); hi3 = fmaxf(n2, t2);
            lo0 = fminf(shvOld, shv); hi0 = fmaxf(shvOld, shv);
            shvOld = shv;
            n0 = t0; n1 = t1; n2 = t2; n3 = t3;
        }
        dp += 8 * 32;
    }

    if (tid == 127)
        out[b] = res * 0.69314718055994531f;           // log2 -> natural domain
}

extern "C" void kernel_launch(void* const* d_in, const int* in_sizes, int n_in,
                              void* d_out, int out_size)
{
    (void)in_sizes; (void)n_in; (void)out_size;
    const float* X = (const float*)d_in[0];
    const float* Y = (const float*)d_in[1];
    float* out = (float*)d_out;

    dim3 g1(NM / 64, NM / 64, BATCH);
    pairdist_kernel<<<g1, 256>>>(X, Y);
    sdtw_kernel<<<BATCH, 128>>>(out);
}

// round 17
// speedup vs baseline: 1.1200x; 1.0326x over previous
#include <cuda_runtime.h>
#include <cuda_bf16.h>
#include <cstdint>

#define NM     512
#define BATCH  32
#define DIMK   64
#define BIGF   1e30f
#define SENTU  0x7fc00000u

// Packed D (pre-scaled by log2 e): g_Dq[b][W][u][k] as float2.
// W = warp row-group (rows 64W+2k, 64W+2k+1), u = local step, col j = u-2k.
#define UROWS 592
__device__ __align__(16) float g_Dq[(size_t)BATCH * 8 * UROWS * 64];

// Boundary rings: producer (warp w) publishes v1(u-1) at slot u.
// value(col c) lives at slot c+63. Slots 0..575 written; rest preinit BIG.
#define RING 656

__device__ __forceinline__ float ex2f(float x) {
    float r; asm("ex2.approx.f32 %0, %1;" : "=f"(r) : "f"(x)); return r;
}
__device__ __forceinline__ float lg2f(float x) {
    float r; asm("lg2.approx.f32 %0, %1;" : "=f"(r) : "f"(x)); return r;
}
// smem spin (raw backward branch, no BSSY): wait until *p != sentinel.
__device__ __forceinline__ float spinv(const float* p) {
    unsigned a = (unsigned)__cvta_generic_to_shared(p);
    unsigned v;
    asm volatile(
        "{\n\t.reg .pred sp;\n"
        "SPINS%=:\n\t"
        "ld.volatile.shared.b32 %0, [%1];\n\t"
        "setp.eq.u32 sp, %0, 0x7fc00000;\n\t"
        "@sp bra SPINS%=;\n\t}"
        : "=r"(v) : "r"(a) : "memory");
    return __uint_as_float(v);
}
__device__ __forceinline__ void sts_vol(float* p, float v) {
    unsigned a = (unsigned)__cvta_generic_to_shared(p);
    asm volatile("st.volatile.shared.b32 [%0], %1;" :: "r"(a), "f"(v) : "memory");
}

// ---------------------------------------------------------------------------
// Kernel 1: pairwise sqdist * log2(e) packed into g_Dq.
// 64x64 tiles (i-tile == warp row-group W), 256 threads, 4x4 microtiles.
// ---------------------------------------------------------------------------
__global__ void __launch_bounds__(256) pairdist_kernel(
    const float* __restrict__ X, const float* __restrict__ Y)
{
    __shared__ __align__(16) float Xs[64 * 68];
    __shared__ __align__(16) float Ys[64 * 68];
    __shared__ __align__(16) float x2s[64];
    __shared__ __align__(16) float y2s[64];
    __shared__ __align__(16) float stage[64 * 66];   // stage[jl*66 + il]

    const int b  = blockIdx.z;
    const int i0 = blockIdx.x * 64;                  // W = blockIdx.x
    const int j0 = blockIdx.y * 64;
    const int tid = threadIdx.x;

    const float* Xb = X + ((size_t)b * NM + i0) * DIMK;
    const float* Yb = Y + ((size_t)b * NM + j0) * DIMK;

    for (int t = tid; t < 64 * 64; t += 256) {
        int r = t >> 6, k = t & 63;
        Xs[k * 68 + r] = Xb[r * DIMK + k];
        Ys[k * 68 + r] = Yb[r * DIMK + k];
    }
    __syncthreads();

    if (tid < 128) {
        int r = tid & 63;
        const float* S = (tid < 64) ? Xs : Ys;
        float acc = 0.f;
        #pragma unroll 8
        for (int k = 0; k < 64; ++k) { float v = S[k * 68 + r]; acc += v * v; }
        if (tid < 64) x2s[r] = acc; else y2s[r] = acc;
    }
    __syncthreads();

    const int tx = tid & 15, ty = tid >> 4;
    float acc[4][4];
    #pragma unroll
    for (int a = 0; a < 4; ++a)
        #pragma unroll
        for (int c = 0; c < 4; ++c) acc[a][c] = 0.f;

    #pragma unroll 8
    for (int k = 0; k < 64; ++k) {
        float4 xv = *(const float4*)&Xs[k * 68 + 4 * tx];
        float4 yv = *(const float4*)&Ys[k * 68 + 4 * ty];
        float xr[4] = {xv.x, xv.y, xv.z, xv.w};
        float yr[4] = {yv.x, yv.y, yv.z, yv.w};
        #pragma unroll
        for (int jj = 0; jj < 4; ++jj)
            #pragma unroll
            for (int ii = 0; ii < 4; ++ii)
                acc[jj][ii] += yr[jj] * xr[ii];
    }

    const float L2E = 1.4426950408889634f;
    float4 x2v = *(const float4*)&x2s[4 * tx];
    float xr2[4] = {x2v.x, x2v.y, x2v.z, x2v.w};
    #pragma unroll
    for (int jj = 0; jj < 4; ++jj) {
        float y2 = y2s[4 * ty + jj];
        #pragma unroll
        for (int ii = 0; ii < 4; ++ii)
            stage[(4 * ty + jj) * 66 + 4 * tx + ii] =
                (xr2[ii] + y2 - 2.f * acc[jj][ii]) * L2E;
    }
    __syncthreads();

    // Packed writeout: local step row c = jl + 2k; lane = k.
    const int wk   = tid >> 5;
    const int lane = tid & 31;
    float2* gout = (float2*)g_Dq + ((size_t)(b * 8 + blockIdx.x) * UROWS + j0) * 32;
    for (int c = wk; c < 126; c += 8) {
        int jl = c - 2 * lane;
        if ((unsigned)jl < 64u) {
            float2 p = *(const float2*)&stage[jl * 66 + 2 * lane];
            gout[(size_t)c * 32 + lane] = p;
        }
    }
}

// ---------------------------------------------------------------------------
// Kernel 2: soft-DTW, skew-2 wavefront, software-pipelined. 1 CTA/batch,
// 8 warps. Lane k of warp w owns rows 64w+2k, +1; local step u covers col
// j = u-2k. Iteration u computes v1(u-1) FIRST (it feeds shfl/ring), then
// v0(u) -- both depend only on previous-iteration state, so the shfl and
// publish overlap the second softmin's MUFU traffic instead of serializing
// after it.
// ---------------------------------------------------------------------------
__global__ void __launch_bounds__(256, 1) sdtw_kernel(float* __restrict__ out)
{
    __shared__ __align__(16) float rings[9][RING];

    const int b    = blockIdx.x;
    const int tid  = threadIdx.x;
    const int w    = tid >> 5;
    const int lane = tid & 31;
    const bool is0  = (lane == 0);
    const bool is31 = (lane == 31);

    for (int t = tid; t < 9 * RING; t += 256) {
        int r = t / RING, s = t % RING;
        bool sent = (r >= 1) && (s < 576);
        rings[0][t] = sent ? __uint_as_float(SENTU) : BIGF;   // flat fill
    }
    __syncthreads();

    // D prefetch ring (float2 per lane per step).
    const float2* dp0 = (const float2*)g_Dq + (size_t)(b * 8 + w) * UROWS * 32 + lane;
    float2 dring[8];
    #pragma unroll
    for (int p = 0; p < 8; ++p) dring[p] = dp0[p * 32];
    const float2* dp = dp0 + 8 * 32;

    const float* rring = rings[w];       // consumer: value(col c) at slot c+63
    float*       wring = rings[w + 1];   // producer: iter u writes slot u

    // Prefill: P(-1) at slot 62, P(0) at slot 63.
    float pm1 = spinv(rring + 62);
    float p0  = spinv(rring + 63);
    if (lane != 0) { pm1 = BIGF; p0 = BIGF; }
    if (w == 0 && lane == 0) pm1 = 0.0f;      // origin: R[-1][-1] = 0
    float lo0  = fminf(pm1, p0), hi0 = fmaxf(pm1, p0);
    float pNow = p0;

    // First chunk: slots 64..71 = P(1..8).
    float bnd[8];
    {
        (void)spinv(rring + 71);
        float4 c0 = *(const float4*)(rring + 64);
        float4 c1 = *(const float4*)(rring + 68);
        bnd[0]=c0.x; bnd[1]=c0.y; bnd[2]=c0.z; bnd[3]=c0.w;
        bnd[4]=c1.x; bnd[5]=c1.y; bnd[6]=c1.z; bnd[7]=c1.w;
    }

    float v0p  = BIGF;                 // v0(u-1)
    float d2yp = 0.f;                  // d(u-1).y
    float lo1p = BIGF, hi1p = BIGF;    // min/max(v0(u-2), v1(u-2))
    float res  = 0.f;

    for (int B = 0; B < 576; B += 8) {
        #pragma unroll
        for (int x = 0; x < 8; ++x) {
            float2 d2 = dring[x];
            dring[x] = dp[x * 32];                 // prefetch step u+8

            // ---- cell1(u-1) FIRST: softmin(v0(u-2), v1(u-2), v0(u-1)).
            // Feeds the ring publish + shfl; short chain, issues immediately.
            float m1  = fminf(lo1p, v0p);
            float x1  = fmaxf(lo1p, v0p);
            float v1m = (d2yp + m1) - lg2f(ex2f(m1 - x1) + ex2f(m1 - hi1p) + 1.0f);

            if (is31) sts_vol(wring + (B + x), v1m);   // publish slot u (early)

            float sh = __shfl_up_sync(0xffffffffu, v1m, 1);
            float newv = is0 ? bnd[x] : sh;            // P(u+1)

            // ---- cell0(u): softmin(P(j-1), P(j), v0(u-1)); overlaps shfl.
            float m0 = fminf(lo0, v0p);
            float x0 = fmaxf(lo0, v0p);
            float v0 = (d2.x + m0) - lg2f(ex2f(m0 - x0) + ex2f(m0 - hi0) + 1.0f);

            if (x == 6) { if (B == 568) res = v1m; }   // iter 574 -> v1(573) = R[511][511]

            if (x == 7) {                              // next chunk: slots B+72..79
                (void)spinv(rring + B + 79);
                float4 c0 = *(const float4*)(rring + B + 72);
                float4 c1 = *(const float4*)(rring + B + 76);
                bnd[0]=c0.x; bnd[1]=c0.y; bnd[2]=c0.z; bnd[3]=c0.w;
                bnd[4]=c1.x; bnd[5]=c1.y; bnd[6]=c1.z; bnd[7]=c1.w;
            }

            // rolls (off the v0 chain)
            lo1p = fminf(v0p, v1m);
            hi1p = fmaxf(v0p, v1m);
            lo0  = fminf(pNow, newv);
            hi0  = fmaxf(pNow, newv);
            pNow = newv;
            v0p  = v0;
            d2yp = d2.y;
        }
        dp += 8 * 32;
    }

    if (tid == 255)
        out[b] = res * 0.69314718055994531f;           // log2 -> natural domain
}

extern "C" void kernel_launch(void* const* d_in, const int* in_sizes, int n_in,
                              void* d_out, int out_size)
{
    (void)in_sizes; (void)n_in; (void)out_size;
    const float* X = (const float*)d_in[0];
    const float* Y = (const float*)d_in[1];
    float* out = (float*)d_out;

    dim3 g1(NM / 64, NM / 64, BATCH);
    pairdist_kernel<<<g1, 256>>>(X, Y);
    sdtw_kernel<<<BATCH, 256>>>(out);
}